// round 16
// baseline (speedup 1.0000x reference)
#include <cuda_runtime.h>
#include <stdint.h>

// out[r, :] = sum over edges (r, c) of weight[c, :]
// adj: [2, nnz] (rows then cols), dtype int64 OR int32 (runtime-detected)
// weight: [size, 256] float32 ; out: [size, 256] float32
//
// R16: fill + gather FUSED into one kernel. 888 blocks (6/SM, guaranteed
// co-resident by __launch_bounds__(256,6), 40-reg cap, no smem) separated
// by a single gen-counter grid barrier. Saves the fill->gather launch
// boundary (~4us) for one ~1.5us barrier. Gather body identical to R13:
// 2-deep metadata pipeline, shfl-broadcast buckets, __stcs stores,
// self-cleaning zero invariant (g_bcount reset by lane 0).

#define OUTF 256
#define MAXN   (1 << 17)   // max rows   (problem: 100000)
#define MAXNNZ (1 << 17)   // max edges  (problem: 100000)
#define CAP 8              // tier-1 slots per row (one 32B wavefront)
#define T2  24             // tier-2 slots per row (deg<=32 total)
#define NB 888             // 6 blocks/SM x 148 SMs (co-resident)

__device__ int g_bcount[MAXN];             // per-row count (zero invariant)
__device__ int g_slots[MAXN * CAP + 32];   // tier-1 (count-gated, no init)
__device__ int g_slots2[MAXN * T2];        // tier-2 (count-gated, no init)
__device__ unsigned g_bar_count;           // returns to 0 each barrier
__device__ unsigned g_bar_gen;             // monotonic across graph replays

// ---------------------------------------------------------- grid barrier
__device__ __forceinline__ void grid_barrier() {
    __syncthreads();
    if (threadIdx.x == 0) {
        __threadfence();
        unsigned gen = *(volatile unsigned*)&g_bar_gen;  // read BEFORE arrive
        if (atomicAdd(&g_bar_count, 1u) == NB - 1) {
            g_bar_count = 0;
            __threadfence();
            atomicAdd(&g_bar_gen, 1u);                   // release
        } else {
            while (*(volatile unsigned*)&g_bar_gen == gen) { }
        }
        __threadfence();
    }
    __syncthreads();
}

// ---------------------------------------------------------------- helpers
__device__ __forceinline__ int detect_is64_warp(const void* adj, long long n,
                                                int n_check, int lane) {
    // int64 indices are all in [0, n); int32-pairs read as int64 are out
    // of range w.h.p. over 64 samples. Warp-collective ballot.
    const long long* a = (const long long*)adj;
    int ok = 1;
    for (int k = lane; k < n_check; k += 32) {
        long long v = a[k];
        if (v < 0 || v >= n) ok = 0;
    }
    unsigned m = __ballot_sync(0xFFFFFFFFu, ok);
    return (m == 0xFFFFFFFFu) ? 1 : 0;
}

// ------------------------------------------------ gather: one-row body
__device__ __forceinline__ void gather_row(
    const float4* __restrict__ w, float* __restrict__ out,
    const void* __restrict__ adj, int nnz, int n,
    int row, int cnt, int slot, int lane)
{
    float4 a0 = make_float4(0.f, 0.f, 0.f, 0.f);
    float4 a1 = make_float4(0.f, 0.f, 0.f, 0.f);

    if (cnt <= CAP + T2) {                            // normal path
        const int m = min(cnt, CAP);
        int k = 0;
        for (; k + 2 <= m; k += 2) {                  // independent pair
            int ca = __shfl_sync(0xFFFFFFFFu, slot, k);
            int cb = __shfl_sync(0xFFFFFFFFu, slot, k + 1);
            const float4* pa = w + (size_t)ca * 64;
            const float4* pb = w + (size_t)cb * 64;
            float4 va0 = __ldg(pa + lane);
            float4 va1 = __ldg(pa + lane + 32);
            float4 vb0 = __ldg(pb + lane);
            float4 vb1 = __ldg(pb + lane + 32);
            a0.x += va0.x + vb0.x; a0.y += va0.y + vb0.y;
            a0.z += va0.z + vb0.z; a0.w += va0.w + vb0.w;
            a1.x += va1.x + vb1.x; a1.y += va1.y + vb1.y;
            a1.z += va1.z + vb1.z; a1.w += va1.w + vb1.w;
        }
        if (k < m) {
            int ca = __shfl_sync(0xFFFFFFFFu, slot, k);
            const float4* pa = w + (size_t)ca * 64;
            float4 va0 = __ldg(pa + lane);
            float4 va1 = __ldg(pa + lane + 32);
            a0.x += va0.x; a0.y += va0.y; a0.z += va0.z; a0.w += va0.w;
            a1.x += va1.x; a1.y += va1.y; a1.z += va1.z; a1.w += va1.w;
        }
        for (int t = CAP; t < cnt; t++) {             // tier-2 (rare)
            int c = __ldg(&g_slots2[row * T2 + (t - CAP)]);
            const float4* p = w + (size_t)c * 64;
            float4 v0 = __ldg(p + lane);
            float4 v1 = __ldg(p + lane + 32);
            a0.x += v0.x; a0.y += v0.y; a0.z += v0.z; a0.w += v0.w;
            a1.x += v1.x; a1.y += v1.y; a1.z += v1.z; a1.w += v1.w;
        }
    } else {
        // Adversarial row (deg > 32): exact stateless rescan of adj.
        int is64 = detect_is64_warp(adj, (long long)n,
                                    nnz < 64 ? nnz : 64, lane);
        if (is64) {
            const long long* a = (const long long*)adj;
            for (int e = 0; e < nnz; e++) {
                if ((int)a[e] == row) {
                    const float4* p = w + (size_t)((int)a[nnz + e]) * 64;
                    float4 v0 = __ldg(p + lane);
                    float4 v1 = __ldg(p + lane + 32);
                    a0.x += v0.x; a0.y += v0.y; a0.z += v0.z; a0.w += v0.w;
                    a1.x += v1.x; a1.y += v1.y; a1.z += v1.z; a1.w += v1.w;
                }
            }
        } else {
            const int* a = (const int*)adj;
            for (int e = 0; e < nnz; e++) {
                if (a[e] == row) {
                    const float4* p = w + (size_t)a[nnz + e] * 64;
                    float4 v0 = __ldg(p + lane);
                    float4 v1 = __ldg(p + lane + 32);
                    a0.x += v0.x; a0.y += v0.y; a0.z += v0.z; a0.w += v0.w;
                    a1.x += v1.x; a1.y += v1.y; a1.z += v1.z; a1.w += v1.w;
                }
            }
        }
    }

    float4* o = (float4*)out + (size_t)row * 64;
    __stcs(o + lane, a0);          // evict-first: out never re-read,
    __stcs(o + lane + 32, a1);     // keep L2 for duplicate weight rows
    if (lane == 0) g_bcount[row] = 0;   // restore zero invariant
}

// -------------------------------------- fused fill + barrier + gather
__global__ void __launch_bounds__(256, 6)
fused_kernel(const void* __restrict__ adj,
             const float* __restrict__ weight,
             float* __restrict__ out,
             int n, int nnz, int n_check) {
    const int lane = threadIdx.x & 31;

    // ---- Phase 1: bucket fill (grid-stride over edges) ----
    {
        const int is64 = detect_is64_warp(adj, (long long)n, n_check, lane);
        int e = blockIdx.x * 256 + threadIdx.x;
        const int stride = NB * 256;
        if (is64) {
            const long long* a = (const long long*)adj;
            for (; e < nnz; e += stride) {
                int r = (int)a[e];
                int c = (int)a[nnz + e];
                int pos = atomicAdd(&g_bcount[r], 1);
                if (pos < CAP)           g_slots[r * CAP + pos] = c;
                else if (pos < CAP + T2) g_slots2[r * T2 + (pos - CAP)] = c;
                // pos >= 32: dropped; gather rescans adj for this row.
            }
        } else {
            const int* a = (const int*)adj;
            for (; e < nnz; e += stride) {
                int r = a[e];
                int c = a[nnz + e];
                int pos = atomicAdd(&g_bcount[r], 1);
                if (pos < CAP)           g_slots[r * CAP + pos] = c;
                else if (pos < CAP + T2) g_slots2[r * T2 + (pos - CAP)] = c;
            }
        }
    }

    grid_barrier();

    // ---- Phase 2: gather (grid-stride over rows, 2-deep pipeline) ----
    {
        const int warp   = (blockIdx.x * 256 + threadIdx.x) >> 5;
        const int nwarps = NB * 8;
        const float4* w  = (const float4*)weight;

        int row = warp;
        if (row >= n) return;

        int cnt  = __ldg(&g_bcount[row]);
        int slot = __ldg(&g_slots[row * CAP + (lane & (CAP - 1))]);

        while (true) {
            int nrow = row + nwarps;
            int ncnt = 0, nslot = 0;
            if (nrow < n) {               // prefetch next row's metadata
                ncnt  = __ldg(&g_bcount[nrow]);
                nslot = __ldg(&g_slots[nrow * CAP + (lane & (CAP - 1))]);
            }

            gather_row(w, out, adj, nnz, n, row, cnt, slot, lane);

            if (nrow >= n) break;
            row = nrow; cnt = ncnt; slot = nslot;
        }
    }
}

// --------------------------------------------- fallback (capacity exceed)
__device__ int g_fb_is64;
__global__ void fb_detect_kernel(const long long* __restrict__ adj,
                                 long long nrows, int n_check) {
    if (threadIdx.x < 32) {
        int ok = 1;
        for (int k = threadIdx.x; k < n_check; k += 32) {
            long long v = adj[k];
            if (v < 0 || v >= nrows) ok = 0;
        }
        unsigned m = __ballot_sync(0xFFFFFFFFu, ok);
        if (threadIdx.x == 0) g_fb_is64 = (m == 0xFFFFFFFFu) ? 1 : 0;
    }
}
__global__ void zero_kernel(float4* __restrict__ out, long long n4) {
    long long i = (long long)blockIdx.x * blockDim.x + threadIdx.x;
    long long stride = (long long)gridDim.x * blockDim.x;
    float4 z = make_float4(0.f, 0.f, 0.f, 0.f);
    for (; i < n4; i += stride) out[i] = z;
}
__global__ void __launch_bounds__(256)
scatter_kernel(const void* __restrict__ adj,
               const float* __restrict__ weight,
               float* __restrict__ out, int nnz) {
    int edge = blockIdx.x * 4 + (threadIdx.x >> 6);
    int t = threadIdx.x & 63;
    if (edge >= nnz) return;
    long long r, c;
    if (g_fb_is64) {
        const long long* a = (const long long*)adj;
        r = a[edge]; c = a[nnz + edge];
    } else {
        const int* a = (const int*)adj;
        r = a[edge]; c = a[nnz + edge];
    }
    float4 v = __ldg((const float4*)(weight + c * OUTF) + t);
    float* o = out + r * OUTF + (long long)t * 4;
    atomicAdd(o + 0, v.x);
    atomicAdd(o + 1, v.y);
    atomicAdd(o + 2, v.z);
    atomicAdd(o + 3, v.w);
}

extern "C" void kernel_launch(void* const* d_in, const int* in_sizes, int n_in,
                              void* d_out, int out_size) {
    const void* adj = d_in[0];
    const float* weight = (const float*)d_in[2];
    float* out = (float*)d_out;

    int nnz = in_sizes[0] / 2;
    int n = out_size / OUTF;
    int n_check = nnz < 64 ? nnz : 64;

    if (n <= MAXN && nnz <= MAXNNZ) {
        fused_kernel<<<NB, 256>>>(adj, weight, out, n, nnz, n_check);
    } else {
        fb_detect_kernel<<<1, 32>>>((const long long*)adj, (long long)n,
                                    n_check);
        long long n4 = (long long)out_size / 4;
        int zblocks = (int)((n4 + 255) / 256);
        if (zblocks < 1) zblocks = 1;
        zero_kernel<<<zblocks, 256>>>((float4*)out, n4);
        int sblocks = (nnz + 3) / 4;
        if (sblocks < 1) sblocks = 1;
        scatter_kernel<<<sblocks, 256>>>(adj, weight, out, nnz);
    }
}